// round 1
// baseline (speedup 1.0000x reference)
#include <cuda_runtime.h>
#include <math.h>

#define NN 100000
#define EE 3200000
#define BB 1000
#define FIN 128
#define S 12          // padded row stride (floats): 10 data + count slot + pad, 48B = 16B aligned

// Scratch (static device globals: no allocation anywhere)
__device__ float g_p [NN * S];   // x @ W1[0:128]
__device__ float g_y [NN * S];   // x @ W1[128:256], slot10 = 1.0 (degree carrier)
__device__ float g_s1[NN * S];   // edge-accumulated y (slot10 = in-degree)
__device__ float g_q [NN * S];   // h @ W2[0:10]
__device__ float g_z [NN * S];   // h @ W2[10:20], slot10 = 1.0
__device__ float g_s2[NN * S];   // edge-accumulated z
__device__ float g_g [BB * S];   // pooled h2 per graph (slot10 = node count)

__device__ __forceinline__ void red_add_v4(float* p, float a, float b, float c, float d) {
    asm volatile("red.global.add.v4.f32 [%0], {%1,%2,%3,%4};"
                 :: "l"(p), "f"(a), "f"(b), "f"(c), "f"(d) : "memory");
}

// ---------------------------------------------------------------------------
// K1: per-node projection. p = x @ W1[0:128,:], y = x @ W1[128:256,:]
// ---------------------------------------------------------------------------
__global__ void k1_project(const float* __restrict__ x, const float* __restrict__ W1) {
    __shared__ float sW[2 * FIN * 10];            // 2560 floats = 10 KB
    for (int i = threadIdx.x; i < 2 * FIN * 10; i += blockDim.x) sW[i] = W1[i];
    __syncthreads();

    int n = blockIdx.x * blockDim.x + threadIdx.x;
    if (n >= NN) return;

    float accP[10], accY[10];
#pragma unroll
    for (int j = 0; j < 10; j++) { accP[j] = 0.f; accY[j] = 0.f; }

    const float4* xr = (const float4*)(x + (size_t)n * FIN);
#pragma unroll 4
    for (int f4 = 0; f4 < FIN / 4; f4++) {
        float4 xv = xr[f4];
        float xf[4] = {xv.x, xv.y, xv.z, xv.w};
#pragma unroll
        for (int k = 0; k < 4; k++) {
            int f = f4 * 4 + k;
            const float* wp = &sW[f * 10];
            const float* wy = &sW[(FIN + f) * 10];
#pragma unroll
            for (int j = 0; j < 10; j++) {
                accP[j] += xf[k] * wp[j];
                accY[j] += xf[k] * wy[j];
            }
        }
    }

    float* pr = g_p + (size_t)n * S;
    float* yr = g_y + (size_t)n * S;
#pragma unroll
    for (int j = 0; j < 10; j++) { pr[j] = accP[j]; yr[j] = accY[j]; }
    pr[10] = 0.f; pr[11] = 0.f;
    yr[10] = 1.f; yr[11] = 0.f;   // degree carrier
}

// ---------------------------------------------------------------------------
// K2/K4: edge scatter: out[dst] += vals[src]  (12 floats via 3x v4 RED)
// ---------------------------------------------------------------------------
__global__ void k_edge_scatter(const int* __restrict__ src, const int* __restrict__ dst,
                               const float* __restrict__ vals, float* __restrict__ outbuf) {
    int e = blockIdx.x * blockDim.x + threadIdx.x;
    if (e >= EE) return;
    int s = src[e], d = dst[e];
    const float4* v = (const float4*)(vals + (size_t)s * S);
    float4 a = v[0], b = v[1], c = v[2];
    float* o = outbuf + (size_t)d * S;
    red_add_v4(o + 0, a.x, a.y, a.z, a.w);
    red_add_v4(o + 4, b.x, b.y, b.z, b.w);
    red_add_v4(o + 8, c.x, c.y, c.z, c.w);
}

// ---------------------------------------------------------------------------
// K3: h = relu(p + s1/deg); q = h @ W2[0:10,:], z = h @ W2[10:20,:]
// ---------------------------------------------------------------------------
__global__ void k3_layer2in(const float* __restrict__ W2) {
    __shared__ float sW[200];
    for (int i = threadIdx.x; i < 200; i += blockDim.x) sW[i] = W2[i];
    __syncthreads();

    int n = blockIdx.x * blockDim.x + threadIdx.x;
    if (n >= NN) return;

    const float* pr = g_p + (size_t)n * S;
    const float* sr = g_s1 + (size_t)n * S;
    float inv = 1.f / fmaxf(sr[10], 1.f);

    float h[10];
#pragma unroll
    for (int j = 0; j < 10; j++)
        h[j] = fmaxf(pr[j] + sr[j] * inv, 0.f);

    float q[10], z[10];
#pragma unroll
    for (int j = 0; j < 10; j++) { q[j] = 0.f; z[j] = 0.f; }
#pragma unroll
    for (int k = 0; k < 10; k++) {
        const float* wq = &sW[k * 10];
        const float* wz = &sW[(10 + k) * 10];
#pragma unroll
        for (int j = 0; j < 10; j++) {
            q[j] += h[k] * wq[j];
            z[j] += h[k] * wz[j];
        }
    }

    float* qr = g_q + (size_t)n * S;
    float* zr = g_z + (size_t)n * S;
#pragma unroll
    for (int j = 0; j < 10; j++) { qr[j] = q[j]; zr[j] = z[j]; }
    qr[10] = 0.f; qr[11] = 0.f;
    zr[10] = 1.f; zr[11] = 0.f;   // node-count carrier reused as degree carrier
}

// ---------------------------------------------------------------------------
// K5: h2 = q + s2/deg; pool into g[batch[n]] (slot10 accumulates node count)
// ---------------------------------------------------------------------------
__global__ void k5_pool(const int* __restrict__ batch) {
    int n = blockIdx.x * blockDim.x + threadIdx.x;
    if (n >= NN) return;

    const float* qr = g_q + (size_t)n * S;
    const float* sr = g_s2 + (size_t)n * S;
    float inv = 1.f / fmaxf(sr[10], 1.f);

    float h2[12];
#pragma unroll
    for (int j = 0; j < 10; j++) h2[j] = qr[j] + sr[j] * inv;
    h2[10] = 1.f; h2[11] = 0.f;

    int b = batch[n];
    float* o = g_g + (size_t)b * S;
    red_add_v4(o + 0, h2[0], h2[1], h2[2],  h2[3]);
    red_add_v4(o + 4, h2[4], h2[5], h2[6],  h2[7]);
    red_add_v4(o + 8, h2[8], h2[9], h2[10], h2[11]);
}

// ---------------------------------------------------------------------------
// K6: out[b] = sigmoid( (sum_g / cnt) . Wfc )
// ---------------------------------------------------------------------------
__global__ void k6_head(const float* __restrict__ Wfc, float* __restrict__ out) {
    int b = blockIdx.x * blockDim.x + threadIdx.x;
    if (b >= BB) return;
    const float* gr = g_g + (size_t)b * S;
    float inv = 1.f / fmaxf(gr[10], 1.f);
    float v = 0.f;
#pragma unroll
    for (int j = 0; j < 10; j++) v += gr[j] * Wfc[j];
    v *= inv;
    out[b] = 1.f / (1.f + expf(-v));
}

// ---------------------------------------------------------------------------
extern "C" void kernel_launch(void* const* d_in, const int* in_sizes, int n_in,
                              void* d_out, int out_size) {
    const float* x     = (const float*)d_in[0];
    const int*   ei    = (const int*)  d_in[1];   // [2, E]: src = ei[0:E), dst = ei[E:2E)
    const int*   batch = (const int*)  d_in[2];
    const float* W1    = (const float*)d_in[3];
    const float* W2    = (const float*)d_in[4];
    const float* Wfc   = (const float*)d_in[5];
    float*       out   = (float*)d_out;

    void *p_s1, *p_s2, *p_g, *p_y, *p_z;
    cudaGetSymbolAddress(&p_s1, g_s1);
    cudaGetSymbolAddress(&p_s2, g_s2);
    cudaGetSymbolAddress(&p_g,  g_g);
    cudaGetSymbolAddress(&p_y,  g_y);
    cudaGetSymbolAddress(&p_z,  g_z);

    cudaMemsetAsync(p_s1, 0, (size_t)NN * S * sizeof(float));
    cudaMemsetAsync(p_s2, 0, (size_t)NN * S * sizeof(float));
    cudaMemsetAsync(p_g,  0, (size_t)BB * S * sizeof(float));

    const int T = 256;
    k1_project   <<<(NN + T - 1) / T, T>>>(x, W1);
    k_edge_scatter<<<(EE + T - 1) / T, T>>>(ei, ei + EE, (const float*)p_y, (float*)p_s1);
    k3_layer2in  <<<(NN + T - 1) / T, T>>>(W2);
    k_edge_scatter<<<(EE + T - 1) / T, T>>>(ei, ei + EE, (const float*)p_z, (float*)p_s2);
    k5_pool      <<<(NN + T - 1) / T, T>>>(batch);
    k6_head      <<<(BB + T - 1) / T, T>>>(Wfc, out);
}

// round 2
// speedup vs baseline: 1.3953x; 1.3953x over previous
#include <cuda_runtime.h>
#include <cuda_fp16.h>
#include <math.h>

#define NN 100000
#define EE 3200000
#define BB 1000
#define FIN 128
#define SF 12         // fp32 row stride (p, q, g): 10 data + count + pad
#define SH 16         // fp16 row stride (messages/accumulators): 32B = 1 sector

// Scratch (static device globals: no allocation anywhere)
__device__ float  g_p [NN * SF];   // x @ W1[0:128]               (fp32)
__device__ __half g_y [NN * SH];   // x @ W1[128:256], slot10=1.0 (fp16 message)
__device__ __half g_s1[NN * SH];   // edge-accumulated y          (fp16 accumulator)
__device__ float  g_q [NN * SF];   // h @ W2[0:10]                (fp32)
__device__ __half g_z [NN * SH];   // h @ W2[10:20], slot10=1.0   (fp16 message)
__device__ __half g_s2[NN * SH];   // edge-accumulated z          (fp16 accumulator)
__device__ float  g_g [BB * SF];   // pooled h2 per graph, slot10 = node count

__device__ __forceinline__ void red_add_v4_f32(float* p, float a, float b, float c, float d) {
    asm volatile("red.global.add.v4.f32 [%0], {%1,%2,%3,%4};"
                 :: "l"(p), "f"(a), "f"(b), "f"(c), "f"(d) : "memory");
}
__device__ __forceinline__ void red_add_v4_h2(void* p, unsigned a, unsigned b, unsigned c, unsigned d) {
    asm volatile("red.global.add.noftz.v4.f16x2 [%0], {%1,%2,%3,%4};"
                 :: "l"(p), "r"(a), "r"(b), "r"(c), "r"(d) : "memory");
}
__device__ __forceinline__ void red_add_v2_h2(void* p, unsigned a, unsigned b) {
    asm volatile("red.global.add.noftz.v2.f16x2 [%0], {%1,%2};"
                 :: "l"(p), "r"(a), "r"(b) : "memory");
}

__device__ __forceinline__ unsigned pack_h2(float lo, float hi) {
    __half2 h = __floats2half2_rn(lo, hi);
    return *(unsigned*)&h;
}

// ---------------------------------------------------------------------------
// K1: per-node projection. p = x @ W1[0:128,:] (fp32), y = x @ W1[128:256,:] (fp16)
// ---------------------------------------------------------------------------
__global__ void k1_project(const float* __restrict__ x, const float* __restrict__ W1) {
    __shared__ float sW[2 * FIN * 10];            // 10 KB
    for (int i = threadIdx.x; i < 2 * FIN * 10; i += blockDim.x) sW[i] = W1[i];
    __syncthreads();

    int n = blockIdx.x * blockDim.x + threadIdx.x;
    if (n >= NN) return;

    float accP[10], accY[10];
#pragma unroll
    for (int j = 0; j < 10; j++) { accP[j] = 0.f; accY[j] = 0.f; }

    const float4* xr = (const float4*)(x + (size_t)n * FIN);
#pragma unroll 4
    for (int f4 = 0; f4 < FIN / 4; f4++) {
        float4 xv = xr[f4];
        float xf[4] = {xv.x, xv.y, xv.z, xv.w};
#pragma unroll
        for (int k = 0; k < 4; k++) {
            int f = f4 * 4 + k;
            const float* wp = &sW[f * 10];
            const float* wy = &sW[(FIN + f) * 10];
#pragma unroll
            for (int j = 0; j < 10; j++) {
                accP[j] += xf[k] * wp[j];
                accY[j] += xf[k] * wy[j];
            }
        }
    }

    float* pr = g_p + (size_t)n * SF;
#pragma unroll
    for (int j = 0; j < 10; j++) pr[j] = accP[j];

    // y row: 16 halves, slots 0-9 data, slot10 = 1.0 (degree carrier), rest 0
    uint4 u0, u1;
    u0.x = pack_h2(accY[0], accY[1]);
    u0.y = pack_h2(accY[2], accY[3]);
    u0.z = pack_h2(accY[4], accY[5]);
    u0.w = pack_h2(accY[6], accY[7]);
    u1.x = pack_h2(accY[8], accY[9]);
    u1.y = pack_h2(1.0f, 0.0f);
    u1.z = 0; u1.w = 0;
    uint4* yr = (uint4*)(g_y + (size_t)n * SH);
    yr[0] = u0; yr[1] = u1;
}

// ---------------------------------------------------------------------------
// K2/K4: edge scatter fp16: acc[dst] += msg[src]  (24B via v4.f16x2 + v2.f16x2)
// ---------------------------------------------------------------------------
__global__ void k_edge_scatter(const int* __restrict__ src, const int* __restrict__ dst,
                               const __half* __restrict__ msg, __half* __restrict__ acc) {
    int e = blockIdx.x * blockDim.x + threadIdx.x;
    if (e >= EE) return;
    int s = src[e], d = dst[e];
    const uint4* v = (const uint4*)(msg + (size_t)s * SH);
    uint4 a = v[0];                         // slots 0-7
    uint2 b = ((const uint2*)v)[2];         // slots 8-11 (incl. count slot 10)
    __half* o = acc + (size_t)d * SH;
    red_add_v4_h2(o, a.x, a.y, a.z, a.w);
    red_add_v2_h2(o + 8, b.x, b.y);
}

// ---------------------------------------------------------------------------
// K3: h = relu(p + s1/deg); q = h @ W2[0:10,:] (fp32), z = h @ W2[10:20,:] (fp16)
// ---------------------------------------------------------------------------
__global__ void k3_layer2in(const float* __restrict__ W2) {
    __shared__ float sW[200];
    for (int i = threadIdx.x; i < 200; i += blockDim.x) sW[i] = W2[i];
    __syncthreads();

    int n = blockIdx.x * blockDim.x + threadIdx.x;
    if (n >= NN) return;

    const float* pr = g_p + (size_t)n * SF;
    const uint4* sv = (const uint4*)(g_s1 + (size_t)n * SH);
    uint4 a = sv[0];
    uint2 b = ((const uint2*)sv)[2];

    float s[12];
    {
        float2 t;
        t = __half22float2(*(__half2*)&a.x); s[0] = t.x; s[1] = t.y;
        t = __half22float2(*(__half2*)&a.y); s[2] = t.x; s[3] = t.y;
        t = __half22float2(*(__half2*)&a.z); s[4] = t.x; s[5] = t.y;
        t = __half22float2(*(__half2*)&a.w); s[6] = t.x; s[7] = t.y;
        t = __half22float2(*(__half2*)&b.x); s[8] = t.x; s[9] = t.y;
        t = __half22float2(*(__half2*)&b.y); s[10] = t.x; s[11] = t.y;
    }
    float inv = 1.f / fmaxf(s[10], 1.f);

    float h[10];
#pragma unroll
    for (int j = 0; j < 10; j++)
        h[j] = fmaxf(pr[j] + s[j] * inv, 0.f);

    float q[10], z[10];
#pragma unroll
    for (int j = 0; j < 10; j++) { q[j] = 0.f; z[j] = 0.f; }
#pragma unroll
    for (int k = 0; k < 10; k++) {
        const float* wq = &sW[k * 10];
        const float* wz = &sW[(10 + k) * 10];
#pragma unroll
        for (int j = 0; j < 10; j++) {
            q[j] += h[k] * wq[j];
            z[j] += h[k] * wz[j];
        }
    }

    float* qr = g_q + (size_t)n * SF;
#pragma unroll
    for (int j = 0; j < 10; j++) qr[j] = q[j];

    uint4 u0, u1;
    u0.x = pack_h2(z[0], z[1]);
    u0.y = pack_h2(z[2], z[3]);
    u0.z = pack_h2(z[4], z[5]);
    u0.w = pack_h2(z[6], z[7]);
    u1.x = pack_h2(z[8], z[9]);
    u1.y = pack_h2(1.0f, 0.0f);
    u1.z = 0; u1.w = 0;
    uint4* zr = (uint4*)(g_z + (size_t)n * SH);
    zr[0] = u0; zr[1] = u1;
}

// ---------------------------------------------------------------------------
// K5: h2 = q + s2/deg; pool (fp32) into g[batch[n]] (slot10 = node count)
// ---------------------------------------------------------------------------
__global__ void k5_pool(const int* __restrict__ batch) {
    int n = blockIdx.x * blockDim.x + threadIdx.x;
    if (n >= NN) return;

    const float* qr = g_q + (size_t)n * SF;
    const uint4* sv = (const uint4*)(g_s2 + (size_t)n * SH);
    uint4 a = sv[0];
    uint2 b = ((const uint2*)sv)[2];

    float s[12];
    {
        float2 t;
        t = __half22float2(*(__half2*)&a.x); s[0] = t.x; s[1] = t.y;
        t = __half22float2(*(__half2*)&a.y); s[2] = t.x; s[3] = t.y;
        t = __half22float2(*(__half2*)&a.z); s[4] = t.x; s[5] = t.y;
        t = __half22float2(*(__half2*)&a.w); s[6] = t.x; s[7] = t.y;
        t = __half22float2(*(__half2*)&b.x); s[8] = t.x; s[9] = t.y;
        t = __half22float2(*(__half2*)&b.y); s[10] = t.x; s[11] = t.y;
    }
    float inv = 1.f / fmaxf(s[10], 1.f);

    float h2[12];
#pragma unroll
    for (int j = 0; j < 10; j++) h2[j] = qr[j] + s[j] * inv;
    h2[10] = 1.f; h2[11] = 0.f;

    int bg = batch[n];
    float* o = g_g + (size_t)bg * SF;
    red_add_v4_f32(o + 0, h2[0], h2[1], h2[2],  h2[3]);
    red_add_v4_f32(o + 4, h2[4], h2[5], h2[6],  h2[7]);
    red_add_v4_f32(o + 8, h2[8], h2[9], h2[10], h2[11]);
}

// ---------------------------------------------------------------------------
// K6: out[b] = sigmoid( (sum_g / cnt) . Wfc )
// ---------------------------------------------------------------------------
__global__ void k6_head(const float* __restrict__ Wfc, float* __restrict__ out) {
    int b = blockIdx.x * blockDim.x + threadIdx.x;
    if (b >= BB) return;
    const float* gr = g_g + (size_t)b * SF;
    float inv = 1.f / fmaxf(gr[10], 1.f);
    float v = 0.f;
#pragma unroll
    for (int j = 0; j < 10; j++) v += gr[j] * Wfc[j];
    v *= inv;
    out[b] = 1.f / (1.f + expf(-v));
}

// ---------------------------------------------------------------------------
extern "C" void kernel_launch(void* const* d_in, const int* in_sizes, int n_in,
                              void* d_out, int out_size) {
    const float* x     = (const float*)d_in[0];
    const int*   ei    = (const int*)  d_in[1];   // [2, E]: src = ei[0:E), dst = ei[E:2E)
    const int*   batch = (const int*)  d_in[2];
    const float* W1    = (const float*)d_in[3];
    const float* W2    = (const float*)d_in[4];
    const float* Wfc   = (const float*)d_in[5];
    float*       out   = (float*)d_out;

    void *p_s1, *p_s2, *p_g, *p_y, *p_z;
    cudaGetSymbolAddress(&p_s1, g_s1);
    cudaGetSymbolAddress(&p_s2, g_s2);
    cudaGetSymbolAddress(&p_g,  g_g);
    cudaGetSymbolAddress(&p_y,  g_y);
    cudaGetSymbolAddress(&p_z,  g_z);

    cudaMemsetAsync(p_s1, 0, (size_t)NN * SH * sizeof(__half));
    cudaMemsetAsync(p_s2, 0, (size_t)NN * SH * sizeof(__half));
    cudaMemsetAsync(p_g,  0, (size_t)BB * SF * sizeof(float));

    const int T = 256;
    k1_project    <<<(NN + T - 1) / T, T>>>(x, W1);
    k_edge_scatter<<<(EE + T - 1) / T, T>>>(ei, ei + EE, (const __half*)p_y, (__half*)p_s1);
    k3_layer2in   <<<(NN + T - 1) / T, T>>>(W2);
    k_edge_scatter<<<(EE + T - 1) / T, T>>>(ei, ei + EE, (const __half*)p_z, (__half*)p_s2);
    k5_pool       <<<(NN + T - 1) / T, T>>>(batch);
    k6_head       <<<(BB + T - 1) / T, T>>>(Wfc, out);
}